// round 4
// baseline (speedup 1.0000x reference)
#include <cuda_runtime.h>
#include <math.h>
#include <stdint.h>

// Problem: s=4096, b=8, D=1280, H=16, DH=80, W=64, nw=64
// QKV GEMM : M=32768, N=3840, K=1280  (NT, both K-major)
// ATTN     : 32768 independent 16x16x80 attention problems
// PROJ GEMM: M=8192,  N=1280, K=5120  (NT)

#define CTA_M 128
#define CTA_N 256
// smem per buffer: A 2048 words (8KB) + B 4096 words (16KB) = 6144 words
#define BUF_WORDS 6144

// Scratch (device globals; no runtime allocation allowed)
__device__ float g_qkv[125829120ull];   // 32768 * 3840
__device__ float g_attn[41943040ull];   // 8192 * 5120

__device__ __forceinline__ uint32_t f2tf32(float x) {
    uint32_t r;
    asm("cvt.rna.tf32.f32 %0, %1;" : "=r"(r) : "f"(x));
    return r;
}

// ---------------------------------------------------------------------------
// C[M,N] = A[M,K] * B[N,K]^T + bias[N], tf32 mma.sync, fp32 accumulate.
// CTA tile 128x256, 8 warps (2x4), warp tile 64x64, BK=16.
// Fragment-major smem: each thread's mma fragment is 4 contiguous words ->
// mainloop fragment loads are conflict-free LDS.128 (8 per warp per k8).
// ---------------------------------------------------------------------------
__global__ __launch_bounds__(256, 1) void tgemm_nt_bias(
    const float* __restrict__ A, const float* __restrict__ B,
    const float* __restrict__ bias, float* __restrict__ C,
    int M, int N, int K)
{
    extern __shared__ __align__(16) uint32_t sm[];   // 2 * BUF_WORDS

    const int tid  = threadIdx.x;
    const int wid  = tid >> 5;
    const int lane = tid & 31;
    const int grp  = lane >> 2;   // 0..7
    const int qid  = lane & 3;    // 0..3

    const int wm = (wid & 1);     // warp M index (0..1) -> rows wm*64
    const int wn = (wid >> 1);    // warp N index (0..3) -> cols wn*64

    // staging decode (A): slot s0 = tid (kc=0), s1 = tid+256 (kc=1)
    const int a_mblk = (tid >> 5) & 7;   // m-block 0..7 (16 rows each)

    const float* Ab = A + (size_t)blockIdx.y * CTA_M * K;
    const float* Bb = B + (size_t)blockIdx.x * CTA_N * K;

    float acc[4][8][4];
#pragma unroll
    for (int i = 0; i < 4; i++)
#pragma unroll
        for (int j = 0; j < 8; j++)
#pragma unroll
            for (int c = 0; c < 4; c++) acc[i][j][c] = 0.f;

    const int nk = K >> 4;

    float ra[8], rb[16];

    // ---- staging helpers (macros keep everything in registers) ----
#define LOAD_TILE(k0)                                                          \
    do {                                                                       \
        const float* pa =                                                      \
            Ab + (size_t)(a_mblk * 16 + grp) * K + (k0) + qid;                 \
        _Pragma("unroll") for (int kc = 0; kc < 2; kc++) {                     \
            const float* p = pa + kc * 8;                                      \
            ra[kc * 4 + 0] = p[0];                                             \
            ra[kc * 4 + 1] = p[(size_t)8 * K];                                 \
            ra[kc * 4 + 2] = p[4];                                             \
            ra[kc * 4 + 3] = p[(size_t)8 * K + 4];                             \
        }                                                                      \
        _Pragma("unroll") for (int j = 0; j < 4; j++) {                        \
            const int kc = j >> 1;                                             \
            const int np = ((tid >> 5) & 7) + (j & 1) * 8;                     \
            const float* p =                                                   \
                Bb + (size_t)(np * 16 + grp) * K + (k0) + kc * 8 + qid;        \
            rb[j * 4 + 0] = p[0];                                              \
            rb[j * 4 + 1] = p[4];                                              \
            rb[j * 4 + 2] = p[(size_t)8 * K];                                  \
            rb[j * 4 + 3] = p[(size_t)8 * K + 4];                              \
        }                                                                      \
    } while (0)

#define STORE_TILE(bufsel)                                                     \
    do {                                                                       \
        uint32_t* buf = sm + (bufsel) * BUF_WORDS;                             \
        uint4 v;                                                               \
        v.x = f2tf32(ra[0]); v.y = f2tf32(ra[1]);                              \
        v.z = f2tf32(ra[2]); v.w = f2tf32(ra[3]);                              \
        *(uint4*)(buf + (a_mblk * 32 + lane) * 4) = v;                         \
        v.x = f2tf32(ra[4]); v.y = f2tf32(ra[5]);                              \
        v.z = f2tf32(ra[6]); v.w = f2tf32(ra[7]);                              \
        *(uint4*)(buf + ((8 + a_mblk) * 32 + lane) * 4) = v;                   \
        uint32_t* bbuf = buf + 2048;                                           \
        _Pragma("unroll") for (int j = 0; j < 4; j++) {                        \
            const int kc = j >> 1;                                             \
            const int np = ((tid >> 5) & 7) + (j & 1) * 8;                     \
            v.x = f2tf32(rb[j * 4 + 0]); v.y = f2tf32(rb[j * 4 + 1]);          \
            v.z = f2tf32(rb[j * 4 + 2]); v.w = f2tf32(rb[j * 4 + 3]);          \
            *(uint4*)(bbuf + ((kc * 16 + np) * 32 + lane) * 4) = v;            \
        }                                                                      \
    } while (0)

    // prologue
    LOAD_TILE(0);
    STORE_TILE(0);
    __syncthreads();

    for (int kt = 0; kt < nk; kt++) {
        if (kt + 1 < nk) LOAD_TILE((kt + 1) << 4);

        const uint32_t* buf = sm + (kt & 1) * BUF_WORDS;
#pragma unroll
        for (int kc = 0; kc < 2; kc++) {
            const uint32_t* ab = buf + (kc * 8 + wm * 4) * 128;
            const uint32_t* bb = buf + 2048 + (kc * 16 + wn * 4) * 128;
            uint4 af[4];
#pragma unroll
            for (int mf = 0; mf < 4; mf++)
                af[mf] = *(const uint4*)(ab + mf * 128 + lane * 4);
#pragma unroll
            for (int np = 0; np < 4; np++) {
                uint4 bf = *(const uint4*)(bb + np * 128 + lane * 4);
#pragma unroll
                for (int mf = 0; mf < 4; mf++) {
                    asm volatile(
                        "mma.sync.aligned.m16n8k8.row.col.f32.tf32.tf32.f32 "
                        "{%0,%1,%2,%3}, {%4,%5,%6,%7}, {%8,%9}, {%0,%1,%2,%3};"
                        : "+f"(acc[mf][np * 2][0]), "+f"(acc[mf][np * 2][1]),
                          "+f"(acc[mf][np * 2][2]), "+f"(acc[mf][np * 2][3])
                        : "r"(af[mf].x), "r"(af[mf].y),
                          "r"(af[mf].z), "r"(af[mf].w),
                          "r"(bf.x), "r"(bf.y));
                    asm volatile(
                        "mma.sync.aligned.m16n8k8.row.col.f32.tf32.tf32.f32 "
                        "{%0,%1,%2,%3}, {%4,%5,%6,%7}, {%8,%9}, {%0,%1,%2,%3};"
                        : "+f"(acc[mf][np * 2 + 1][0]), "+f"(acc[mf][np * 2 + 1][1]),
                          "+f"(acc[mf][np * 2 + 1][2]), "+f"(acc[mf][np * 2 + 1][3])
                        : "r"(af[mf].x), "r"(af[mf].y),
                          "r"(af[mf].z), "r"(af[mf].w),
                          "r"(bf.z), "r"(bf.w));
                }
            }
        }

        if (kt + 1 < nk) STORE_TILE((kt + 1) & 1);
        __syncthreads();
    }

    // epilogue: bias + float2 stores
#pragma unroll
    for (int mf = 0; mf < 4; mf++) {
        const int row0 = blockIdx.y * CTA_M + wm * 64 + mf * 16 + grp;
#pragma unroll
        for (int nb = 0; nb < 8; nb++) {
            const int col = blockIdx.x * CTA_N + wn * 64 + nb * 8 + qid * 2;
            const float bv0 = bias[col], bv1 = bias[col + 1];
            float2 r0 = make_float2(acc[mf][nb][0] + bv0, acc[mf][nb][1] + bv1);
            float2 r1 = make_float2(acc[mf][nb][2] + bv0, acc[mf][nb][3] + bv1);
            *(float2*)(C + (size_t)row0 * N + col) = r0;
            *(float2*)(C + (size_t)(row0 + 8) * N + col) = r1;
        }
    }
#undef LOAD_TILE
#undef STORE_TILE
}

// ---------------------------------------------------------------------------
// Windowed attention: one block per qkv row r = (n*64+w)*8 + b.
// S[h,g] = q_h . k_g / sqrt(80); softmax over g; O = P V.
// Scatter-writes the rearranged (nw*H, b, W*DH) layout.
// ---------------------------------------------------------------------------
__global__ __launch_bounds__(256) void attn_kernel(const float* __restrict__ qkv,
                                                   float* __restrict__ O2)
{
    __shared__ float qs[16 * 84];
    __shared__ float ks[16 * 84];
    __shared__ float vs[16 * 84];
    __shared__ float sc[16][17];

    const int r    = blockIdx.x;
    const int b    = r & 7;
    const int sidx = r >> 3;
    const int w    = sidx & 63;
    const int n    = sidx >> 6;
    const int tid  = threadIdx.x;

    const float* row = qkv + (size_t)r * 3840;
    for (int i = tid; i < 1280; i += 256) {
        int h = i / 80, d = i - h * 80;
        qs[h * 84 + d] = row[i];
        ks[h * 84 + d] = row[1280 + i];
        vs[h * 84 + d] = row[2560 + i];
    }
    __syncthreads();

    {
        const int h = tid >> 4, g = tid & 15;
        const float* qh = qs + h * 84;
        const float* kg = ks + g * 84;
        float s = 0.f;
#pragma unroll
        for (int d = 0; d < 80; d++) s = fmaf(qh[d], kg[d], s);
        sc[h][g] = s * 0.11180339887498948f;
    }
    __syncthreads();

    if (tid < 16) {
        float m = sc[tid][0];
#pragma unroll
        for (int g = 1; g < 16; g++) m = fmaxf(m, sc[tid][g]);
        float sum = 0.f;
#pragma unroll
        for (int g = 0; g < 16; g++) {
            float e = expf(sc[tid][g] - m);
            sc[tid][g] = e;
            sum += e;
        }
        float inv = 1.f / sum;
#pragma unroll
        for (int g = 0; g < 16; g++) sc[tid][g] *= inv;
    }
    __syncthreads();

    float* obase = O2 + ((size_t)(n * 16) * 8 + b) * 5120 + (size_t)w * 80;
    for (int i = tid; i < 1280; i += 256) {
        int h = i / 80, d = i - h * 80;
        float o = 0.f;
#pragma unroll
        for (int g = 0; g < 16; g++) o = fmaf(sc[h][g], vs[g * 84 + d], o);
        obase[(size_t)h * 8 * 5120 + d] = o;
    }
}

// ---------------------------------------------------------------------------
// Launcher
// Inputs: 0=x (4096,8,1280) f32, 1=cu_seqlens i64 (ignored), 2=qkv_w (3840,1280),
//         3=qkv_b (3840), 4=proj_w (1280,5120), 5=proj_b (1280)
// Output: (1024, 8, 1280) f32
// ---------------------------------------------------------------------------
extern "C" void kernel_launch(void* const* d_in, const int* in_sizes, int n_in,
                              void* d_out, int out_size)
{
    const float* x      = (const float*)d_in[0];
    const float* qkv_w  = (const float*)d_in[2];
    const float* qkv_b  = (const float*)d_in[3];
    const float* proj_w = (const float*)d_in[4];
    const float* proj_b = (const float*)d_in[5];
    float* out = (float*)d_out;

    float *qkv_buf, *attn_buf;
    cudaGetSymbolAddress((void**)&qkv_buf, g_qkv);
    cudaGetSymbolAddress((void**)&attn_buf, g_attn);

    const int smem_bytes = 2 * BUF_WORDS * 4;  // 49152
    cudaFuncSetAttribute(tgemm_nt_bias,
                         cudaFuncAttributeMaxDynamicSharedMemorySize, smem_bytes);

    // 1) QKV projection: (32768 x 1280) @ (3840 x 1280)^T + bias
    tgemm_nt_bias<<<dim3(3840 / CTA_N, 32768 / CTA_M), 256, smem_bytes>>>(
        x, qkv_w, qkv_b, qkv_buf, 32768, 3840, 1280);

    // 2) Windowed attention over head axis, scatter to rearranged layout
    attn_kernel<<<32768, 256>>>(qkv_buf, attn_buf);

    // 3) Output projection: (8192 x 5120) @ (1280 x 5120)^T + bias -> d_out
    tgemm_nt_bias<<<dim3(1280 / CTA_N, 8192 / CTA_M), 256, smem_bytes>>>(
        attn_buf, proj_w, proj_b, out, 8192, 1280, 5120);
}